// round 7
// baseline (speedup 1.0000x reference)
#include <cuda_runtime.h>
#include <cuda_fp16.h>
#include <mma.h>
#include <cstdint>

using namespace nvcuda;

// Scratch (__device__ globals; runtime alloc forbidden)
__device__ __half g_xa [14680064];  // [64 j1][1024 b][224 kpad]   fp16
__device__ __half g_k1t[14680064];  // [64 j1][1024 l1][224 kpad]  fp16
__device__ __half g_k3t[16777216];  // [64 j3][256 l3pad][1024 k3] fp16
__device__ __half g_h1p[67108864];  // [64 j1][16 r][64 p2][1024 b] fp16
__device__ __half g_h2r[67108864];  // [64 j3][1024 b][1024 k3]     fp16

__device__ __forceinline__ uint32_t smem_u32(const void* p) {
    uint32_t a;
    asm("{ .reg .u64 t; cvta.to.shared.u64 t, %1; cvt.u32.u64 %0, t; }"
        : "=r"(a) : "l"(p));
    return a;
}
__device__ __forceinline__ void cpa(uint32_t d, const void* s) {
    asm volatile("cp.async.cg.shared.global [%0], [%1], 16;" :: "r"(d), "l"(s));
}
__device__ __forceinline__ void cpcommit() { asm volatile("cp.async.commit_group;" ::: "memory"); }
__device__ __forceinline__ void cpwait0()  { asm volatile("cp.async.wait_group 0;" ::: "memory"); }
__device__ __forceinline__ void cpwait1()  { asm volatile("cp.async.wait_group 1;" ::: "memory"); }

// Row stride 56 halves (112B): LDSM row banks (28*r)%32 all distinct per
// 8-row phase => conflict-free fragment loads (validated R5).
#define LDM   56
#define ROWB  112
// A bufs: 128 rows -> 14336 B each @ 0 / 14336
// B bufs: 256 rows -> 28672 B each @ 28672 / 57344.  Total 86016 B.
#define A_OFF(b) ((b) * 14336)
#define B_OFF(b) (28672 + (b) * 28672)
#define SMEM_BYTES 86016

// ------------------------- pre-kernels ------------------------------------
__global__ __launch_bounds__(256) void gather_x(const float* __restrict__ x) {
    const int b = blockIdx.x;
    const int j1 = blockIdx.y * 8 + (threadIdx.x >> 5);
    const int lane = threadIdx.x & 31;
    const int bx = j1 >> 3, by = j1 & 7;
    const float* xr = x + b * 12800;
    __half* dst = g_xa + (j1 * 1024 + b) * 224;
    for (int k = lane; k < 224; k += 32) {
        float v = 0.0f;
        if (k < 200) {
            int q = k >> 1, c = k & 1;
            int wx = q / 10, wy = q - wx * 10;
            v = xr[((bx * 10 + wx) * 80 + by * 10 + wy) * 2 + c];
        }
        dst[k] = __float2half_rn(v);
    }
}
__global__ void transpose_k1(const float* __restrict__ k1) {
    __shared__ float t[32][33];
    const int j1 = blockIdx.z, l0 = blockIdx.x * 32, k0 = blockIdx.y * 32;
    const int tx = threadIdx.x, ty = threadIdx.y;
#pragma unroll
    for (int r = 0; r < 32; r += 8) {
        int k = k0 + ty + r;
        t[ty + r][tx] = (k < 200) ? k1[(j1 * 200 + k) * 1024 + l0 + tx] : 0.0f;
    }
    __syncthreads();
#pragma unroll
    for (int r = 0; r < 32; r += 8)
        g_k1t[(j1 * 1024 + l0 + ty + r) * 224 + k0 + tx] = __float2half_rn(t[tx][ty + r]);
}
__global__ void transpose_k3(const float* __restrict__ k3) {
    __shared__ float t[32][33];
    const int j3 = blockIdx.z, k0 = blockIdx.x * 32, l0 = blockIdx.y * 32;
    const int tx = threadIdx.x, ty = threadIdx.y;
#pragma unroll
    for (int r = 0; r < 32; r += 8) {
        int l = l0 + tx, k = k0 + ty + r;
        t[ty + r][tx] = (l < 200) ? k3[(j3 * 1024 + k) * 200 + l] : 0.0f;
    }
    __syncthreads();
#pragma unroll
    for (int r = 0; r < 32; r += 8)
        g_k3t[(j3 * 256 + l0 + ty + r) * 1024 + k0 + tx] = __float2half_rn(t[tx][ty + r]);
}

// ------------------------- GEMM core (fp16 wmma) ---------------------------
// CTA tile 128(m) x 256(n), k-chunk 32. 8 warps as 2(m) x 4(n), each 64x64.
template <int NC>
__device__ __forceinline__ void gemm_mainloop(
    const __half* aS, int aStride, const __half* bS, int bStride,
    char* dsm, uint32_t sbase, int tid, int wr, int wc,
    wmma::fragment<wmma::accumulator, 16, 16, 16, float> (&acc)[4][4])
{
#pragma unroll
    for (int i = 0; i < 4; i++)
#pragma unroll
        for (int j = 0; j < 4; j++) wmma::fill_fragment(acc[i][j], 0.0f);

    // preload chunk 0 into buf 0
    for (int i = tid; i < 512; i += 256) {
        int row = i >> 2, seg = i & 3;
        cpa(sbase + A_OFF(0) + row * ROWB + seg * 16, aS + row * aStride + seg * 8);
    }
    for (int i = tid; i < 1024; i += 256) {
        int row = i >> 2, seg = i & 3;
        cpa(sbase + B_OFF(0) + row * ROWB + seg * 16, bS + row * bStride + seg * 8);
    }
    cpcommit();

    for (int c = 0; c < NC; c++) {
        const int buf = c & 1;
        if (c + 1 < NC) {
            const int nb = (c + 1) & 1, k0 = (c + 1) * 32;
            for (int i = tid; i < 512; i += 256) {
                int row = i >> 2, seg = i & 3;
                cpa(sbase + A_OFF(nb) + row * ROWB + seg * 16,
                    aS + row * aStride + k0 + seg * 8);
            }
            for (int i = tid; i < 1024; i += 256) {
                int row = i >> 2, seg = i & 3;
                cpa(sbase + B_OFF(nb) + row * ROWB + seg * 16,
                    bS + row * bStride + k0 + seg * 8);
            }
            cpcommit();
            cpwait1();
        } else {
            cpwait0();
        }
        __syncthreads();

        const __half* As = (const __half*)(dsm + A_OFF(buf));
        const __half* Bs = (const __half*)(dsm + B_OFF(buf));
#pragma unroll
        for (int kk = 0; kk < 32; kk += 16) {
            wmma::fragment<wmma::matrix_a, 16, 16, 16, __half, wmma::row_major> af[4];
#pragma unroll
            for (int i = 0; i < 4; i++)
                wmma::load_matrix_sync(af[i], As + (wr * 64 + i * 16) * LDM + kk, LDM);
#pragma unroll
            for (int j = 0; j < 4; j++) {
                wmma::fragment<wmma::matrix_b, 16, 16, 16, __half, wmma::col_major> bf;
                wmma::load_matrix_sync(bf, Bs + (wc * 64 + j * 16) * LDM + kk, LDM);
#pragma unroll
                for (int i = 0; i < 4; i++)
                    wmma::mma_sync(acc[i][j], af[i], bf, acc[i][j]);
            }
        }
        __syncthreads();
    }
}

// ------------------------- GEMM1 ------------------------------------------
__global__ __launch_bounds__(256, 1) void g1(const float* __restrict__ b1) {
    extern __shared__ __align__(16) char dsm[];
    const int tid = threadIdx.x, wid = tid >> 5;
    const int wr = wid >> 2, wc = wid & 3;
    const int j1 = blockIdx.z, n0 = blockIdx.x * 256, m0 = blockIdx.y * 128;
    const uint32_t sbase = smem_u32(dsm);

    const __half* aS = g_xa  + (j1 * 1024 + m0) * 224;
    const __half* bS = g_k1t + (j1 * 1024 + n0) * 224;

    wmma::fragment<wmma::accumulator, 16, 16, 16, float> acc[4][4];
    gemm_mainloop<7>(aS, 224, bS, 224, dsm, sbase, tid, wr, wc, acc);

    float* stage = (float*)dsm;
#pragma unroll
    for (int h = 0; h < 4; ++h) {
        if (wc == h) {
#pragma unroll
            for (int i = 0; i < 4; i++)
#pragma unroll
                for (int j = 0; j < 4; j++)
                    wmma::store_matrix_sync(
                        stage + (wr * 64 + i * 16) * 68 + j * 16,
                        acc[i][j], 68, wmma::mem_row_major);
        }
        __syncthreads();
        for (int e = tid; e < 8192; e += 256) {
            int cc = e >> 7, row = e & 127;
            int l1 = n0 + h * 64 + cc;
            float v = stage[row * 68 + cc] + b1[(j1 << 10) + l1];
            g_h1p[((j1 * 16 + (l1 & 15)) * 64 + (l1 >> 4)) * 1024 + m0 + row] =
                __float2half_rn(v);
        }
        __syncthreads();
    }
}

// ------------------------- GEMM2 (fp32 math, fp16 I/O) ---------------------
__global__ __launch_bounds__(128) void g2(const float* __restrict__ k2,
                                          const float* __restrict__ b2) {
    const int j2 = blockIdx.x, tid = threadIdx.x;
    __shared__ float wgt[256];
    __shared__ float bias[16];
    reinterpret_cast<float2*>(wgt)[tid] =
        reinterpret_cast<const float2*>(k2 + j2 * 256)[tid];
    if (tid < 16) bias[tid] = b2[j2 * 16 + tid];
    __syncthreads();

    const int r = j2 >> 8, j1 = (j2 >> 2) & 63, p2hi = j2 & 3;
    const int b = blockIdx.y * 128 + tid;
    const __half* src = g_h1p + ((j1 * 16 + r) * 64 + p2hi * 16) * 1024 + b;
    float in[16];
#pragma unroll
    for (int k = 0; k < 16; k++) in[k] = __half2float(src[k * 1024]);
    float out[16];
#pragma unroll
    for (int l = 0; l < 16; l++) out[l] = bias[l];
#pragma unroll
    for (int k = 0; k < 16; k++) {
        float a = in[k];
#pragma unroll
        for (int l = 0; l < 16; l++) out[l] += a * wgt[k * 16 + l];
    }
    __half2 ph[8];
#pragma unroll
    for (int q = 0; q < 8; q++)
        ph[q] = __floats2half2_rn(out[2 * q], out[2 * q + 1]);
    __half* dp = g_h2r + ((size_t)(r * 4 + (j1 >> 4)) * 1024 + b) * 1024 +
                 (j1 & 15) * 64 + p2hi * 16;
    reinterpret_cast<uint4*>(dp)[0] = reinterpret_cast<uint4*>(ph)[0];
    reinterpret_cast<uint4*>(dp)[1] = reinterpret_cast<uint4*>(ph)[1];
}

// ------------------------- GEMM3 ------------------------------------------
__global__ __launch_bounds__(256, 1) void g3(const float* __restrict__ b3,
                                             float* __restrict__ out) {
    extern __shared__ __align__(16) char dsm[];
    const int tid = threadIdx.x, wid = tid >> 5;
    const int wr = wid >> 2, wc = wid & 3;
    const int j3 = blockIdx.z, m0 = blockIdx.y * 128;
    const uint32_t sbase = smem_u32(dsm);

    const __half* aS = g_h2r + ((size_t)(j3 * 1024 + m0)) * 1024;
    const __half* bS = g_k3t + ((size_t)(j3 * 256)) * 1024;

    wmma::fragment<wmma::accumulator, 16, 16, 16, float> acc[4][4];
    gemm_mainloop<32>(aS, 1024, bS, 1024, dsm, sbase, tid, wr, wc, acc);

    float* stage = (float*)dsm;
    const int b2x = j3 >> 3, b2y = j3 & 7;
#pragma unroll
    for (int h = 0; h < 4; ++h) {
        if (wc == h) {
#pragma unroll
            for (int i = 0; i < 4; i++)
#pragma unroll
                for (int j = 0; j < 4; j++)
                    wmma::store_matrix_sync(
                        stage + (wr * 64 + i * 16) * 68 + j * 16,
                        acc[i][j], 68, wmma::mem_row_major);
        }
        __syncthreads();
        if (h * 64 < 200) {
            for (int e = tid; e < 8192; e += 256) {
                int cc = e & 63, row = e >> 6;
                int l3 = h * 64 + cc;
                if (l3 < 200) {
                    float v = stage[row * 68 + cc] + b3[j3 * 200 + l3];
                    int q = l3 >> 1, c = l3 & 1;
                    int w2x = q / 10, w2y = q - w2x * 10;
                    out[(m0 + row) * 12800 +
                        ((b2x * 10 + w2x) * 80 + b2y * 10 + w2y) * 2 + c] = v;
                }
            }
        }
        __syncthreads();
    }
}

extern "C" void kernel_launch(void* const* d_in, const int* in_sizes, int n_in,
                              void* d_out, int out_size) {
    const float* x   = (const float*)d_in[0];
    const float* k1  = (const float*)d_in[1];
    const float* b1  = (const float*)d_in[2];
    const float* k2  = (const float*)d_in[3];
    const float* b2  = (const float*)d_in[4];
    const float* k3w = (const float*)d_in[5];
    const float* b3  = (const float*)d_in[6];
    float* out = (float*)d_out;

    cudaFuncSetAttribute(g1, cudaFuncAttributeMaxDynamicSharedMemorySize, SMEM_BYTES);
    cudaFuncSetAttribute(g3, cudaFuncAttributeMaxDynamicSharedMemorySize, SMEM_BYTES);

    gather_x    <<<dim3(1024, 8), 256>>>(x);
    transpose_k1<<<dim3(32, 7, 64), dim3(32, 8)>>>(k1);
    transpose_k3<<<dim3(32, 8, 64), dim3(32, 8)>>>(k3w);
    g1<<<dim3(4, 8, 64), 256, SMEM_BYTES>>>(b1);
    g2<<<dim3(4096, 8), 128>>>(k2, b2);
    g3<<<dim3(1, 8, 64), 256, SMEM_BYTES>>>(b3, out);
}

// round 9
// speedup vs baseline: 1.1300x; 1.1300x over previous
#include <cuda_runtime.h>
#include <cuda_fp16.h>
#include <mma.h>
#include <cstdint>

using namespace nvcuda;

// Scratch (__device__ globals; runtime alloc forbidden)
__device__ __half g_xa [14680064];  // [64 j1][1024 b][224 kpad]   fp16
__device__ __half g_k1t[14680064];  // [64 j1][1024 l1][224 kpad]  fp16
__device__ __half g_k3t[16777216];  // [64 j3][256 l3pad][1024 k3] fp16
__device__ __half g_h2r[67108864];  // [64 j3][1024 b][1024 k3]    fp16
__device__ float  g_b2eff[65536];   // [4096 j2][16]  (b1@k2 + b2)

__device__ __forceinline__ uint32_t smem_u32(const void* p) {
    uint32_t a;
    asm("{ .reg .u64 t; cvta.to.shared.u64 t, %1; cvt.u32.u64 %0, t; }"
        : "=r"(a) : "l"(p));
    return a;
}
__device__ __forceinline__ uint32_t h2_u32(__half2 h) {
    return *reinterpret_cast<const uint32_t*>(&h);
}
__device__ __forceinline__ void cpa(uint32_t d, const void* s) {
    asm volatile("cp.async.cg.shared.global [%0], [%1], 16;" :: "r"(d), "l"(s));
}
__device__ __forceinline__ void cpcommit() { asm volatile("cp.async.commit_group;" ::: "memory"); }
__device__ __forceinline__ void cpwait0()  { asm volatile("cp.async.wait_group 0;" ::: "memory"); }
__device__ __forceinline__ void cpwait1()  { asm volatile("cp.async.wait_group 1;" ::: "memory"); }

// Row stride 56 halves (112B): LDSM banks (28*r)%32 all distinct per 8-row
// phase => conflict-free fragment loads (validated R5).
#define LDM   56
#define ROWB  112
// A bufs (128 rows): 14336 B each @ 0 / 14336
// B bufs (256 rows): 28672 B each @ 28672 / 57344.  Mainloop total 86016 B.
#define A_OFF(b) ((b) * 14336)
#define B_OFF(b) (28672 + (b) * 28672)
// g1 fused epilogue regions:
//   stage2h fp16 [256 l1][ldm 136] @ 0            (69632 B)
//   warpscratch  16 x 1024 B       @ 69632        (-> 86016)
//   k2h fp16     16 x 256          @ 86016        (8192 B)
//   b2eff fp32   16 x 16           @ 94208        (1024 B)
#define S2_LDM   136
#define WSCR_OFF 69632
#define K2H_OFF  86016
#define B2S_OFF  94208
#define G1_SMEM  95232
#define G3_SMEM  86016

// ------------------------- pre-kernels ------------------------------------
__global__ __launch_bounds__(256) void gather_x(const float* __restrict__ x) {
    const int b = blockIdx.x;
    const int j1 = blockIdx.y * 8 + (threadIdx.x >> 5);
    const int lane = threadIdx.x & 31;
    const int bx = j1 >> 3, by = j1 & 7;
    const float* xr = x + b * 12800;
    __half* dst = g_xa + (j1 * 1024 + b) * 224;
    for (int k = lane; k < 224; k += 32) {
        float v = 0.0f;
        if (k < 200) {
            int q = k >> 1, c = k & 1;
            int wx = q / 10, wy = q - wx * 10;
            v = xr[((bx * 10 + wx) * 80 + by * 10 + wy) * 2 + c];
        }
        dst[k] = __float2half_rn(v);
    }
}
__global__ void transpose_k1(const float* __restrict__ k1) {
    __shared__ float t[32][33];
    const int j1 = blockIdx.z, l0 = blockIdx.x * 32, k0 = blockIdx.y * 32;
    const int tx = threadIdx.x, ty = threadIdx.y;
#pragma unroll
    for (int r = 0; r < 32; r += 8) {
        int k = k0 + ty + r;
        t[ty + r][tx] = (k < 200) ? k1[(j1 * 200 + k) * 1024 + l0 + tx] : 0.0f;
    }
    __syncthreads();
#pragma unroll
    for (int r = 0; r < 32; r += 8)
        g_k1t[(j1 * 1024 + l0 + ty + r) * 224 + k0 + tx] = __float2half_rn(t[tx][ty + r]);
}
__global__ void transpose_k3(const float* __restrict__ k3) {
    __shared__ float t[32][33];
    const int j3 = blockIdx.z, k0 = blockIdx.x * 32, l0 = blockIdx.y * 32;
    const int tx = threadIdx.x, ty = threadIdx.y;
#pragma unroll
    for (int r = 0; r < 32; r += 8) {
        int l = l0 + tx, k = k0 + ty + r;
        t[ty + r][tx] = (l < 200) ? k3[(j3 * 1024 + k) * 200 + l] : 0.0f;
    }
    __syncthreads();
#pragma unroll
    for (int r = 0; r < 32; r += 8)
        g_k3t[(j3 * 256 + l0 + ty + r) * 1024 + k0 + tx] = __float2half_rn(t[tx][ty + r]);
}
// b2eff[j2][p] = b2[j2][p] + sum_k b1[j1][(t*16+k)*16 + r] * k2[j2][k][p]
__global__ __launch_bounds__(32) void biasprep(const float* __restrict__ b1,
                                               const float* __restrict__ k2,
                                               const float* __restrict__ b2) {
    const int j2 = blockIdx.x, p = threadIdx.x;
    if (p >= 16) return;
    const int r = j2 >> 8, j1 = (j2 >> 2) & 63, t = j2 & 3;
    float s = b2[j2 * 16 + p];
#pragma unroll
    for (int k = 0; k < 16; k++)
        s += b1[j1 * 1024 + (t * 16 + k) * 16 + r] * k2[j2 * 256 + k * 16 + p];
    g_b2eff[j2 * 16 + p] = s;
}

// ------------------------- shared mainloop (512 thr, 128x256 tile) --------
template <int NC>
__device__ __forceinline__ void gemm_mainloop(
    const __half* aS, int aStride, const __half* bS, int bStride,
    char* dsm, uint32_t sbase, int tid, int wr, int wc,
    wmma::fragment<wmma::accumulator, 16, 16, 16, float> (&acc)[2][4])
{
#pragma unroll
    for (int i = 0; i < 2; i++)
#pragma unroll
        for (int j = 0; j < 4; j++) wmma::fill_fragment(acc[i][j], 0.0f);

    {   // preload chunk 0
        int row = tid >> 2, seg = tid & 3;
        cpa(sbase + A_OFF(0) + row * ROWB + seg * 16, aS + row * aStride + seg * 8);
        for (int i = tid; i < 1024; i += 512) {
            int r2 = i >> 2, s2 = i & 3;
            cpa(sbase + B_OFF(0) + r2 * ROWB + s2 * 16, bS + r2 * bStride + s2 * 8);
        }
        cpcommit();
    }
    for (int c = 0; c < NC; c++) {
        const int buf = c & 1;
        if (c + 1 < NC) {
            const int nb = (c + 1) & 1, k0 = (c + 1) * 32;
            int row = tid >> 2, seg = tid & 3;
            cpa(sbase + A_OFF(nb) + row * ROWB + seg * 16,
                aS + row * aStride + k0 + seg * 8);
            for (int i = tid; i < 1024; i += 512) {
                int r2 = i >> 2, s2 = i & 3;
                cpa(sbase + B_OFF(nb) + r2 * ROWB + s2 * 16,
                    bS + r2 * bStride + k0 + s2 * 8);
            }
            cpcommit();
            cpwait1();
        } else {
            cpwait0();
        }
        __syncthreads();

        const __half* As = (const __half*)(dsm + A_OFF(buf));
        const __half* Bs = (const __half*)(dsm + B_OFF(buf));
#pragma unroll
        for (int kk = 0; kk < 32; kk += 16) {
            wmma::fragment<wmma::matrix_a, 16, 16, 16, __half, wmma::row_major> af[2];
            wmma::fragment<wmma::matrix_b, 16, 16, 16, __half, wmma::col_major> bf[4];
#pragma unroll
            for (int i = 0; i < 2; i++)
                wmma::load_matrix_sync(af[i], As + (wr * 32 + i * 16) * LDM + kk, LDM);
#pragma unroll
            for (int j = 0; j < 4; j++)
                wmma::load_matrix_sync(bf[j], Bs + (wc * 64 + j * 16) * LDM + kk, LDM);
#pragma unroll
            for (int i = 0; i < 2; i++)
#pragma unroll
                for (int j = 0; j < 4; j++)
                    wmma::mma_sync(acc[i][j], af[i], bf[j], acc[i][j]);
        }
        __syncthreads();
    }
}

// ------------------------- GEMM1 fused with GEMM2 --------------------------
__global__ __launch_bounds__(512, 1) void g1f(const float* __restrict__ k2) {
    extern __shared__ __align__(16) char dsm[];
    const int tid = threadIdx.x, wid = tid >> 5, lane = tid & 31;
    const int wr = wid >> 2, wc = wid & 3;
    const int t = blockIdx.x, j1 = blockIdx.z, m0 = blockIdx.y * 128;
    const uint32_t sbase = smem_u32(dsm);

    // preload g2 weights/bias into the region untouched by the mainloop
    {
        __half* k2h = (__half*)(dsm + K2H_OFF);
        float*  b2s = (float*)(dsm + B2S_OFF);
        for (int i = tid; i < 4096; i += 512) {
            int r = i >> 8, kp = i & 255;
            k2h[i] = __float2half_rn(k2[(r * 256 + j1 * 4 + t) * 256 + kp]);
        }
        if (tid < 256) {
            int r = tid >> 4, p = tid & 15;
            b2s[tid] = g_b2eff[(r * 256 + j1 * 4 + t) * 16 + p];
        }
    }

    const __half* aS = g_xa  + (j1 * 1024 + m0) * 224;
    const __half* bS = g_k1t + (j1 * 1024 + t * 256) * 224;

    wmma::fragment<wmma::accumulator, 16, 16, 16, float> acc[2][4];
    gemm_mainloop<7>(aS, 224, bS, 224, dsm, sbase, tid, wr, wc, acc);

    // ---- phase 1: acc -> stage2h [l1_local][b] fp16, ldm 136 ----
    float* wscr = (float*)(dsm + WSCR_OFF + wid * 1024);
    __half* s2h = (__half*)dsm;
#pragma unroll
    for (int i = 0; i < 2; i++) {
#pragma unroll
        for (int j = 0; j < 4; j++) {
            wmma::store_matrix_sync(wscr, acc[i][j], 16, wmma::mem_col_major);
            __syncwarp();
            int l1c = lane >> 1, boff = (lane & 1) * 8;
            float4 v0 = *(float4*)(wscr + l1c * 16 + boff);
            float4 v1 = *(float4*)(wscr + l1c * 16 + boff + 4);
            __half2 h0 = __floats2half2_rn(v0.x, v0.y);
            __half2 h1 = __floats2half2_rn(v0.z, v0.w);
            __half2 h2 = __floats2half2_rn(v1.x, v1.y);
            __half2 h3 = __floats2half2_rn(v1.z, v1.w);
            int n_off = wc * 64 + j * 16, m_off = wr * 32 + i * 16;
            uint4 pk;
            pk.x = h2_u32(h0); pk.y = h2_u32(h1);
            pk.z = h2_u32(h2); pk.w = h2_u32(h3);
            *(uint4*)(s2h + (n_off + l1c) * S2_LDM + m_off + boff) = pk;
            __syncwarp();
        }
    }
    __syncthreads();

    // ---- phase 2: g2 via wmma, warp wid handles r = wid ----
    {
        const __half* k2h = (const __half*)(dsm + K2H_OFF);
        const float*  b2s = (const float*)(dsm + B2S_OFF);
        const int r = wid;
        wmma::fragment<wmma::matrix_b, 16, 16, 16, __half, wmma::row_major> bfr;
        wmma::load_matrix_sync(bfr, k2h + r * 256, 16);
        const size_t obase = ((size_t)(r * 4 + (j1 >> 4)) << 20) +
                             (size_t)(j1 & 15) * 64 + t * 16;
        float b2v[8];
        {
            int poff = (lane & 1) * 8;
#pragma unroll
            for (int q = 0; q < 8; q++) b2v[q] = b2s[r * 16 + poff + q];
        }
#pragma unroll
        for (int mb = 0; mb < 8; mb++) {
            wmma::fragment<wmma::matrix_a, 16, 16, 16, __half, wmma::col_major> afr;
            wmma::load_matrix_sync(afr, s2h + r * S2_LDM + mb * 16, 16 * S2_LDM);
            wmma::fragment<wmma::accumulator, 16, 16, 16, float> oc;
            wmma::fill_fragment(oc, 0.0f);
            wmma::mma_sync(oc, afr, bfr, oc);
            wmma::store_matrix_sync(wscr, oc, 16, wmma::mem_row_major);
            __syncwarp();
            int b = lane >> 1, poff = (lane & 1) * 8;
            float4 v0 = *(float4*)(wscr + b * 16 + poff);
            float4 v1 = *(float4*)(wscr + b * 16 + poff + 4);
            __half2 h0 = __floats2half2_rn(v0.x + b2v[0], v0.y + b2v[1]);
            __half2 h1 = __floats2half2_rn(v0.z + b2v[2], v0.w + b2v[3]);
            __half2 h2 = __floats2half2_rn(v1.x + b2v[4], v1.y + b2v[5]);
            __half2 h3 = __floats2half2_rn(v1.z + b2v[6], v1.w + b2v[7]);
            uint4 pk;
            pk.x = h2_u32(h0); pk.y = h2_u32(h1);
            pk.z = h2_u32(h2); pk.w = h2_u32(h3);
            *(uint4*)(g_h2r + obase + (size_t)(m0 + mb * 16 + b) * 1024 + poff) = pk;
            __syncwarp();
        }
    }
}

// ------------------------- GEMM3 (512 thr, 128x256) ------------------------
__global__ __launch_bounds__(512, 1) void g3(const float* __restrict__ b3,
                                             float* __restrict__ out) {
    extern __shared__ __align__(16) char dsm[];
    const int tid = threadIdx.x, wid = tid >> 5;
    const int wr = wid >> 2, wc = wid & 3;
    const int j3 = blockIdx.z, m0 = blockIdx.y * 128;
    const uint32_t sbase = smem_u32(dsm);

    const __half* aS = g_h2r + ((size_t)(j3 * 1024 + m0)) * 1024;
    const __half* bS = g_k3t + ((size_t)(j3 * 256)) * 1024;

    wmma::fragment<wmma::accumulator, 16, 16, 16, float> acc[2][4];
    gemm_mainloop<32>(aS, 1024, bS, 1024, dsm, sbase, tid, wr, wc, acc);

    float* stage = (float*)dsm;
    const int b2x = j3 >> 3, b2y = j3 & 7;
#pragma unroll
    for (int h = 0; h < 4; ++h) {
        if (wc == h) {
#pragma unroll
            for (int i = 0; i < 2; i++)
#pragma unroll
                for (int j = 0; j < 4; j++)
                    wmma::store_matrix_sync(
                        stage + (wr * 32 + i * 16) * 68 + j * 16,
                        acc[i][j], 68, wmma::mem_row_major);
        }
        __syncthreads();
        if (h * 64 < 200) {
            for (int e = tid; e < 8192; e += 512) {
                int cc = e & 63, row = e >> 6;
                int l3 = h * 64 + cc;
                if (l3 < 200) {
                    float v = stage[row * 68 + cc] + b3[j3 * 200 + l3];
                    int q = l3 >> 1, c = l3 & 1;
                    int w2x = q / 10, w2y = q - w2x * 10;
                    out[(m0 + row) * 12800 +
                        ((b2x * 10 + w2x) * 80 + b2y * 10 + w2y) * 2 + c] = v;
                }
            }
        }
        __syncthreads();
    }
}

extern "C" void kernel_launch(void* const* d_in, const int* in_sizes, int n_in,
                              void* d_out, int out_size) {
    const float* x   = (const float*)d_in[0];
    const float* k1  = (const float*)d_in[1];
    const float* b1  = (const float*)d_in[2];
    const float* k2  = (const float*)d_in[3];
    const float* b2  = (const float*)d_in[4];
    const float* k3w = (const float*)d_in[5];
    const float* b3  = (const float*)d_in[6];
    float* out = (float*)d_out;

    cudaFuncSetAttribute(g1f, cudaFuncAttributeMaxDynamicSharedMemorySize, G1_SMEM);
    cudaFuncSetAttribute(g3,  cudaFuncAttributeMaxDynamicSharedMemorySize, G3_SMEM);

    gather_x    <<<dim3(1024, 8), 256>>>(x);
    transpose_k1<<<dim3(32, 7, 64), dim3(32, 8)>>>(k1);
    transpose_k3<<<dim3(32, 8, 64), dim3(32, 8)>>>(k3w);
    biasprep    <<<4096, 32>>>(b1, k2, b2);
    g1f<<<dim3(4, 8, 64), 512, G1_SMEM>>>(k2);
    g3 <<<dim3(1, 8, 64), 512, G3_SMEM>>>(b3, out);
}

// round 10
// speedup vs baseline: 1.2532x; 1.1090x over previous
#include <cuda_runtime.h>
#include <cuda_fp16.h>
#include <mma.h>
#include <cstdint>

using namespace nvcuda;

// Scratch (__device__ globals; runtime alloc forbidden)
__device__ __half g_xa [16777216];  // [64 j1][1024 b][256 kpad]   fp16
__device__ __half g_k1t[16777216];  // [64 j1][1024 l1][256 kpad]  fp16
__device__ __half g_k3t[16777216];  // [64 j3][256 l3pad][1024 k3] fp16
__device__ __half g_h1p[67108864];  // [64 j1][16 r][64 p2][1024 b] fp16
__device__ __half g_h2r[67108864];  // [64 j3][1024 b][1024 k3]     fp16

__device__ __forceinline__ uint32_t smem_u32(const void* p) {
    uint32_t a;
    asm("{ .reg .u64 t; cvta.to.shared.u64 t, %1; cvt.u32.u64 %0, t; }"
        : "=r"(a) : "l"(p));
    return a;
}
__device__ __forceinline__ void cpa(uint32_t d, const void* s) {
    asm volatile("cp.async.cg.shared.global [%0], [%1], 16;" :: "r"(d), "l"(s));
}
__device__ __forceinline__ void cpcommit() { asm volatile("cp.async.commit_group;" ::: "memory"); }
__device__ __forceinline__ void cpwait0()  { asm volatile("cp.async.wait_group 0;" ::: "memory"); }
__device__ __forceinline__ void cpwait1()  { asm volatile("cp.async.wait_group 1;" ::: "memory"); }

// k-chunk 64. Row stride 72 halves (144B): LDSM banks (36*r)%32 =
// {0,4,8,12,16,20,24,28} all distinct per 8-row phase => conflict-free.
#define LDM   72
#define ROWB  144
// A bufs (128 rows x 144B = 18432 B) @ 0 / 18432
// B bufs (128 rows)                 @ 36864 / 55296.  Total 73728 B.
#define A_OFF(b) ((b) * 18432)
#define B_OFF(b) (36864 + (b) * 18432)
#define SMEM_BYTES 73728

// ------------------------- pre-kernels ------------------------------------
__global__ __launch_bounds__(256) void gather_x(const float* __restrict__ x) {
    const int b = blockIdx.x;
    const int j1 = blockIdx.y * 8 + (threadIdx.x >> 5);
    const int lane = threadIdx.x & 31;
    const int bx = j1 >> 3, by = j1 & 7;
    const float* xr = x + b * 12800;
    __half* dst = g_xa + (j1 * 1024 + b) * 256;
    for (int k = lane; k < 256; k += 32) {
        float v = 0.0f;
        if (k < 200) {
            int q = k >> 1, c = k & 1;
            int wx = q / 10, wy = q - wx * 10;
            v = xr[((bx * 10 + wx) * 80 + by * 10 + wy) * 2 + c];
        }
        dst[k] = __float2half_rn(v);
    }
}
__global__ void transpose_k1(const float* __restrict__ k1) {
    __shared__ float t[32][33];
    const int j1 = blockIdx.z, l0 = blockIdx.x * 32, k0 = blockIdx.y * 32;
    const int tx = threadIdx.x, ty = threadIdx.y;
#pragma unroll
    for (int r = 0; r < 32; r += 8) {
        int k = k0 + ty + r;
        t[ty + r][tx] = (k < 200) ? k1[(j1 * 200 + k) * 1024 + l0 + tx] : 0.0f;
    }
    __syncthreads();
#pragma unroll
    for (int r = 0; r < 32; r += 8)
        g_k1t[(j1 * 1024 + l0 + ty + r) * 256 + k0 + tx] = __float2half_rn(t[tx][ty + r]);
}
__global__ void transpose_k3(const float* __restrict__ k3) {
    __shared__ float t[32][33];
    const int j3 = blockIdx.z, k0 = blockIdx.x * 32, l0 = blockIdx.y * 32;
    const int tx = threadIdx.x, ty = threadIdx.y;
#pragma unroll
    for (int r = 0; r < 32; r += 8) {
        int l = l0 + tx, k = k0 + ty + r;
        t[ty + r][tx] = (l < 200) ? k3[(j3 * 1024 + k) * 200 + l] : 0.0f;
    }
    __syncthreads();
#pragma unroll
    for (int r = 0; r < 32; r += 8)
        g_k3t[(j3 * 256 + l0 + ty + r) * 1024 + k0 + tx] = __float2half_rn(t[tx][ty + r]);
}

// ------------------------- GEMM core (fp16 wmma) ---------------------------
// CTA tile 128(m) x 128(n), k-chunk 64, 8 warps as 4(m) x 2(n), each 32x64.
template <int NC>
__device__ __forceinline__ void gemm_mainloop(
    const __half* aS, int aStride, const __half* bS, int bStride,
    char* dsm, uint32_t sbase, int tid, int wr, int wc,
    wmma::fragment<wmma::accumulator, 16, 16, 16, float> (&acc)[2][4])
{
#pragma unroll
    for (int i = 0; i < 2; i++)
#pragma unroll
        for (int j = 0; j < 4; j++) wmma::fill_fragment(acc[i][j], 0.0f);

    // preload chunk 0 into buf 0  (128 rows x 128 B = 8 segs of 16B)
    for (int i = tid; i < 1024; i += 256) {
        int row = i >> 3, seg = i & 7;
        cpa(sbase + A_OFF(0) + row * ROWB + seg * 16, aS + row * aStride + seg * 8);
        cpa(sbase + B_OFF(0) + row * ROWB + seg * 16, bS + row * bStride + seg * 8);
    }
    cpcommit();

    for (int c = 0; c < NC; c++) {
        const int buf = c & 1;
        if (c + 1 < NC) {
            const int nb = (c + 1) & 1, k0 = (c + 1) * 64;
            for (int i = tid; i < 1024; i += 256) {
                int row = i >> 3, seg = i & 7;
                cpa(sbase + A_OFF(nb) + row * ROWB + seg * 16,
                    aS + row * aStride + k0 + seg * 8);
                cpa(sbase + B_OFF(nb) + row * ROWB + seg * 16,
                    bS + row * bStride + k0 + seg * 8);
            }
            cpcommit();
            cpwait1();
        } else {
            cpwait0();
        }
        __syncthreads();

        const __half* As = (const __half*)(dsm + A_OFF(buf));
        const __half* Bs = (const __half*)(dsm + B_OFF(buf));
#pragma unroll
        for (int kk = 0; kk < 64; kk += 16) {
            wmma::fragment<wmma::matrix_a, 16, 16, 16, __half, wmma::row_major> af[2];
            wmma::fragment<wmma::matrix_b, 16, 16, 16, __half, wmma::col_major> bf[4];
#pragma unroll
            for (int i = 0; i < 2; i++)
                wmma::load_matrix_sync(af[i], As + (wr * 32 + i * 16) * LDM + kk, LDM);
#pragma unroll
            for (int j = 0; j < 4; j++)
                wmma::load_matrix_sync(bf[j], Bs + (wc * 64 + j * 16) * LDM + kk, LDM);
#pragma unroll
            for (int i = 0; i < 2; i++)
#pragma unroll
                for (int j = 0; j < 4; j++)
                    wmma::mma_sync(acc[i][j], af[i], bf[j], acc[i][j]);
        }
        __syncthreads();
    }
}

// ------------------------- GEMM1 ------------------------------------------
__global__ __launch_bounds__(256, 2) void g1(const float* __restrict__ b1) {
    extern __shared__ __align__(16) char dsm[];
    const int tid = threadIdx.x, wid = tid >> 5;
    const int wr = wid >> 1, wc = wid & 1;
    const int j1 = blockIdx.z, n0 = blockIdx.x * 128, m0 = blockIdx.y * 128;
    const uint32_t sbase = smem_u32(dsm);

    const __half* aS = g_xa  + (j1 * 1024 + m0) * 256;
    const __half* bS = g_k1t + (j1 * 1024 + n0) * 256;

    wmma::fragment<wmma::accumulator, 16, 16, 16, float> acc[2][4];
    gemm_mainloop<4>(aS, 256, bS, 256, dsm, sbase, tid, wr, wc, acc);

    float* stage = (float*)dsm;
#pragma unroll
    for (int h = 0; h < 2; ++h) {
        if (wc == h) {
#pragma unroll
            for (int i = 0; i < 2; i++)
#pragma unroll
                for (int j = 0; j < 4; j++)
                    wmma::store_matrix_sync(
                        stage + (wr * 32 + i * 16) * 68 + j * 16,
                        acc[i][j], 68, wmma::mem_row_major);
        }
        __syncthreads();
        for (int e = tid; e < 8192; e += 256) {
            int cc = e >> 7, row = e & 127;
            int l1 = n0 + h * 64 + cc;
            float v = stage[row * 68 + cc] + b1[(j1 << 10) + l1];
            g_h1p[((j1 * 16 + (l1 & 15)) * 64 + (l1 >> 4)) * 1024 + m0 + row] =
                __float2half_rn(v);
        }
        __syncthreads();
    }
}

// ------------------------- GEMM2 (fp32 math, fp16 I/O) ---------------------
__global__ __launch_bounds__(128) void g2(const float* __restrict__ k2,
                                          const float* __restrict__ b2) {
    const int j2 = blockIdx.x, tid = threadIdx.x;
    __shared__ float wgt[256];
    __shared__ float bias[16];
    reinterpret_cast<float2*>(wgt)[tid] =
        reinterpret_cast<const float2*>(k2 + j2 * 256)[tid];
    if (tid < 16) bias[tid] = b2[j2 * 16 + tid];
    __syncthreads();

    const int r = j2 >> 8, j1 = (j2 >> 2) & 63, p2hi = j2 & 3;
    const int b = blockIdx.y * 128 + tid;
    const __half* src = g_h1p + ((j1 * 16 + r) * 64 + p2hi * 16) * 1024 + b;
    float in[16];
#pragma unroll
    for (int k = 0; k < 16; k++) in[k] = __half2float(src[k * 1024]);
    float out[16];
#pragma unroll
    for (int l = 0; l < 16; l++) out[l] = bias[l];
#pragma unroll
    for (int k = 0; k < 16; k++) {
        float a = in[k];
#pragma unroll
        for (int l = 0; l < 16; l++) out[l] += a * wgt[k * 16 + l];
    }
    __half2 ph[8];
#pragma unroll
    for (int q = 0; q < 8; q++)
        ph[q] = __floats2half2_rn(out[2 * q], out[2 * q + 1]);
    __half* dp = g_h2r + ((size_t)(r * 4 + (j1 >> 4)) * 1024 + b) * 1024 +
                 (j1 & 15) * 64 + p2hi * 16;
    reinterpret_cast<uint4*>(dp)[0] = reinterpret_cast<uint4*>(ph)[0];
    reinterpret_cast<uint4*>(dp)[1] = reinterpret_cast<uint4*>(ph)[1];
}

// ------------------------- GEMM3 ------------------------------------------
__global__ __launch_bounds__(256, 2) void g3(const float* __restrict__ b3,
                                             float* __restrict__ out) {
    extern __shared__ __align__(16) char dsm[];
    const int tid = threadIdx.x, wid = tid >> 5;
    const int wr = wid >> 1, wc = wid & 1;
    const int j3 = blockIdx.z, n0 = blockIdx.x * 128, m0 = blockIdx.y * 128;
    const uint32_t sbase = smem_u32(dsm);

    const __half* aS = g_h2r + ((size_t)(j3 * 1024 + m0)) * 1024;
    const __half* bS = g_k3t + ((size_t)(j3 * 256 + n0)) * 1024;

    wmma::fragment<wmma::accumulator, 16, 16, 16, float> acc[2][4];
    gemm_mainloop<16>(aS, 1024, bS, 1024, dsm, sbase, tid, wr, wc, acc);

    float* stage = (float*)dsm;
    const int b2x = j3 >> 3, b2y = j3 & 7;
#pragma unroll
    for (int h = 0; h < 2; ++h) {
        if (wc == h) {
#pragma unroll
            for (int i = 0; i < 2; i++)
#pragma unroll
                for (int j = 0; j < 4; j++)
                    wmma::store_matrix_sync(
                        stage + (wr * 32 + i * 16) * 68 + j * 16,
                        acc[i][j], 68, wmma::mem_row_major);
        }
        __syncthreads();
        for (int e = tid; e < 8192; e += 256) {
            int cc = e & 63, row = e >> 6;
            int l3 = n0 + h * 64 + cc;
            if (l3 < 200) {
                float v = stage[row * 68 + cc] + b3[j3 * 200 + l3];
                int q = l3 >> 1, c = l3 & 1;
                int w2x = q / 10, w2y = q - w2x * 10;
                out[(m0 + row) * 12800 +
                    ((b2x * 10 + w2x) * 80 + b2y * 10 + w2y) * 2 + c] = v;
            }
        }
        __syncthreads();
    }
}

extern "C" void kernel_launch(void* const* d_in, const int* in_sizes, int n_in,
                              void* d_out, int out_size) {
    const float* x   = (const float*)d_in[0];
    const float* k1  = (const float*)d_in[1];
    const float* b1  = (const float*)d_in[2];
    const float* k2  = (const float*)d_in[3];
    const float* b2  = (const float*)d_in[4];
    const float* k3w = (const float*)d_in[5];
    const float* b3  = (const float*)d_in[6];
    float* out = (float*)d_out;

    cudaFuncSetAttribute(g1, cudaFuncAttributeMaxDynamicSharedMemorySize, SMEM_BYTES);
    cudaFuncSetAttribute(g3, cudaFuncAttributeMaxDynamicSharedMemorySize, SMEM_BYTES);

    gather_x    <<<dim3(1024, 8), 256>>>(x);
    transpose_k1<<<dim3(32, 8, 64), dim3(32, 8)>>>(k1);
    transpose_k3<<<dim3(32, 8, 64), dim3(32, 8)>>>(k3w);
    g1<<<dim3(8, 8, 64), 256, SMEM_BYTES>>>(b1);
    g2<<<dim3(4096, 8), 128>>>(k2, b2);
    g3<<<dim3(2, 8, 64), 256, SMEM_BYTES>>>(b3, out);
}

// round 11
// speedup vs baseline: 1.4876x; 1.1870x over previous
#include <cuda_runtime.h>
#include <cuda_fp16.h>
#include <mma.h>
#include <cstdint>

using namespace nvcuda;

// Scratch (__device__ globals; runtime alloc forbidden)
__device__ __half g_xa [16777216];  // [64 j1][1024 b][256 kpad]   fp16
__device__ __half g_k1t[16777216];  // [64 j1][1024 l1][256 kpad]  fp16
__device__ __half g_k3t[16777216];  // [64 j3][256 l3pad][1024 k3] fp16
__device__ __half g_h2r[67108864];  // [64 j3][1024 b][1024 k3]    fp16
__device__ float  g_b2eff[65536];   // [4096 j2][16]  (b1@k2 + b2)

__device__ __forceinline__ uint32_t smem_u32(const void* p) {
    uint32_t a;
    asm("{ .reg .u64 t; cvta.to.shared.u64 t, %1; cvt.u32.u64 %0, t; }"
        : "=r"(a) : "l"(p));
    return a;
}
__device__ __forceinline__ uint32_t h2_u32(__half2 h) {
    return *reinterpret_cast<const uint32_t*>(&h);
}
__device__ __forceinline__ void cpa(uint32_t d, const void* s) {
    asm volatile("cp.async.cg.shared.global [%0], [%1], 16;" :: "r"(d), "l"(s));
}
__device__ __forceinline__ void cpcommit() { asm volatile("cp.async.commit_group;" ::: "memory"); }
__device__ __forceinline__ void cpwait0()  { asm volatile("cp.async.wait_group 0;" ::: "memory"); }
__device__ __forceinline__ void cpwait1()  { asm volatile("cp.async.wait_group 1;" ::: "memory"); }

// k-chunk 64. Row stride 72 halves (144B): LDSM banks (36*r)%32 all distinct
// per 8-row phase => conflict-free (validated R10).
#define LDM   72
#define ROWB  144
#define A_OFF(b) ((b) * 18432)
#define B_OFF(b) (36864 + (b) * 18432)
#define SMEM_BYTES 73728          // g3 mainloop-only size
// g1f extra regions (beyond mainloop's 73728):
#define K2H_OFF   73728           // fp16 [8 rr][256]      (4096 B)
#define B2S_OFF   77824           // fp32 [8 rr][16]       (512 B)
#define G1F_SMEM  78336
// epilogue overlays (after mainloop finishes):
#define STG_LDM   136             // fp16 stage [128 cc][136], @0 (34816 B)
#define WSCR_OFF  36864           // fp32 warp scratch, 1KB/warp

// ------------------------- pre-kernels ------------------------------------
__global__ __launch_bounds__(256) void gather_x(const float* __restrict__ x) {
    const int b = blockIdx.x;
    const int j1 = blockIdx.y * 8 + (threadIdx.x >> 5);
    const int lane = threadIdx.x & 31;
    const int bx = j1 >> 3, by = j1 & 7;
    const float* xr = x + b * 12800;
    __half* dst = g_xa + (j1 * 1024 + b) * 256;
    for (int k = lane; k < 256; k += 32) {
        float v = 0.0f;
        if (k < 200) {
            int q = k >> 1, c = k & 1;
            int wx = q / 10, wy = q - wx * 10;
            v = xr[((bx * 10 + wx) * 80 + by * 10 + wy) * 2 + c];
        }
        dst[k] = __float2half_rn(v);
    }
}
__global__ void transpose_k1(const float* __restrict__ k1) {
    __shared__ float t[32][33];
    const int j1 = blockIdx.z, l0 = blockIdx.x * 32, k0 = blockIdx.y * 32;
    const int tx = threadIdx.x, ty = threadIdx.y;
#pragma unroll
    for (int r = 0; r < 32; r += 8) {
        int k = k0 + ty + r;
        t[ty + r][tx] = (k < 200) ? k1[(j1 * 200 + k) * 1024 + l0 + tx] : 0.0f;
    }
    __syncthreads();
#pragma unroll
    for (int r = 0; r < 32; r += 8)
        g_k1t[(j1 * 1024 + l0 + ty + r) * 256 + k0 + tx] = __float2half_rn(t[tx][ty + r]);
}
__global__ void transpose_k3(const float* __restrict__ k3) {
    __shared__ float t[32][33];
    const int j3 = blockIdx.z, k0 = blockIdx.x * 32, l0 = blockIdx.y * 32;
    const int tx = threadIdx.x, ty = threadIdx.y;
#pragma unroll
    for (int r = 0; r < 32; r += 8) {
        int l = l0 + tx, k = k0 + ty + r;
        t[ty + r][tx] = (l < 200) ? k3[(j3 * 1024 + k) * 200 + l] : 0.0f;
    }
    __syncthreads();
#pragma unroll
    for (int r = 0; r < 32; r += 8)
        g_k3t[(j3 * 256 + l0 + ty + r) * 1024 + k0 + tx] = __float2half_rn(t[tx][ty + r]);
}
// b2eff[j2][p] = b2[j2][p] + sum_k b1[j1][(t*16+k)*16 + r] * k2[j2][k][p]
__global__ __launch_bounds__(32) void biasprep(const float* __restrict__ b1,
                                               const float* __restrict__ k2,
                                               const float* __restrict__ b2) {
    const int j2 = blockIdx.x, p = threadIdx.x;
    if (p >= 16) return;
    const int r = j2 >> 8, j1 = (j2 >> 2) & 63, t = j2 & 3;
    float s = b2[j2 * 16 + p];
#pragma unroll
    for (int k = 0; k < 16; k++)
        s += b1[j1 * 1024 + (t * 16 + k) * 16 + r] * k2[j2 * 256 + k * 16 + p];
    g_b2eff[j2 * 16 + p] = s;
}

// ------------------------- GEMM1 fused with GEMM2 --------------------------
// CTA: 128 b-rows x 128 permuted l1-cols for (j1, t=bx>>1, rh=bx&1).
// col cc = rr*16 + p2lo  ->  l1 = (t*16 + p2lo)*16 + rh*8 + rr
__global__ __launch_bounds__(256, 2) void g1f(const float* __restrict__ k2) {
    extern __shared__ __align__(16) char dsm[];
    const int tid = threadIdx.x, wid = tid >> 5, lane = tid & 31;
    const int wr = wid >> 1, wc = wid & 1;
    const int bx = blockIdx.x, j1 = blockIdx.z, m0 = blockIdx.y * 128;
    const int t = bx >> 1, rh = bx & 1;
    const uint32_t sbase = smem_u32(dsm);

    // stage k2 (fp16) + b2eff for this CTA's 8 r values
    {
        __half* k2h = (__half*)(dsm + K2H_OFF);
        float*  b2s = (float*)(dsm + B2S_OFF);
        for (int i = tid; i < 2048; i += 256) {
            int rr = i >> 8, kp = i & 255;
            k2h[i] = __float2half_rn(
                k2[((rh * 8 + rr) * 256 + j1 * 4 + t) * 256 + kp]);
        }
        if (tid < 128) {
            int rr = tid >> 4, p = tid & 15;
            b2s[tid] = g_b2eff[(((rh * 8 + rr) * 256 + j1 * 4 + t) << 4) + p];
        }
    }

    const __half* aS = g_xa  + (j1 * 1024 + m0) * 256;
    const __half* bS = g_k1t + (size_t)j1 * 1024 * 256;

    wmma::fragment<wmma::accumulator, 16, 16, 16, float> acc[2][4];
#pragma unroll
    for (int i = 0; i < 2; i++)
#pragma unroll
        for (int j = 0; j < 4; j++) wmma::fill_fragment(acc[i][j], 0.0f);

    // preload chunk 0
    for (int i = tid; i < 1024; i += 256) {
        int row = i >> 3, seg = i & 7;
        int l1 = ((t * 16 + (row & 15)) << 4) + rh * 8 + (row >> 4);
        cpa(sbase + A_OFF(0) + row * ROWB + seg * 16, aS + row * 256 + seg * 8);
        cpa(sbase + B_OFF(0) + row * ROWB + seg * 16, bS + l1 * 256 + seg * 8);
    }
    cpcommit();

    for (int c = 0; c < 4; c++) {
        const int buf = c & 1;
        if (c + 1 < 4) {
            const int nb = (c + 1) & 1, k0 = (c + 1) * 64;
            for (int i = tid; i < 1024; i += 256) {
                int row = i >> 3, seg = i & 7;
                int l1 = ((t * 16 + (row & 15)) << 4) + rh * 8 + (row >> 4);
                cpa(sbase + A_OFF(nb) + row * ROWB + seg * 16,
                    aS + row * 256 + k0 + seg * 8);
                cpa(sbase + B_OFF(nb) + row * ROWB + seg * 16,
                    bS + l1 * 256 + k0 + seg * 8);
            }
            cpcommit();
            cpwait1();
        } else {
            cpwait0();
        }
        __syncthreads();

        const __half* As = (const __half*)(dsm + A_OFF(buf));
        const __half* Bs = (const __half*)(dsm + B_OFF(buf));
#pragma unroll
        for (int kk = 0; kk < 64; kk += 16) {
            wmma::fragment<wmma::matrix_a, 16, 16, 16, __half, wmma::row_major> af[2];
            wmma::fragment<wmma::matrix_b, 16, 16, 16, __half, wmma::col_major> bf[4];
#pragma unroll
            for (int i = 0; i < 2; i++)
                wmma::load_matrix_sync(af[i], As + (wr * 32 + i * 16) * LDM + kk, LDM);
#pragma unroll
            for (int j = 0; j < 4; j++)
                wmma::load_matrix_sync(bf[j], Bs + (wc * 64 + j * 16) * LDM + kk, LDM);
#pragma unroll
            for (int i = 0; i < 2; i++)
#pragma unroll
                for (int j = 0; j < 4; j++)
                    wmma::mma_sync(acc[i][j], af[i], bf[j], acc[i][j]);
        }
        __syncthreads();
    }

    // ---- epilogue phase A: acc -> fp16 stage[cc][b] (overlays A/B bufs) ----
    __half* stage = (__half*)dsm;
    float* wscr = (float*)(dsm + WSCR_OFF + wid * 1024);
#pragma unroll
    for (int i = 0; i < 2; i++) {
#pragma unroll
        for (int j = 0; j < 4; j++) {
            wmma::store_matrix_sync(wscr, acc[i][j], 16, wmma::mem_col_major);
            __syncwarp();
            int cl = lane >> 1, boff = (lane & 1) * 8;
            float4 v0 = *(float4*)(wscr + cl * 16 + boff);
            float4 v1 = *(float4*)(wscr + cl * 16 + boff + 4);
            __half2 h0 = __floats2half2_rn(v0.x, v0.y);
            __half2 h1 = __floats2half2_rn(v0.z, v0.w);
            __half2 h2 = __floats2half2_rn(v1.x, v1.y);
            __half2 h3 = __floats2half2_rn(v1.z, v1.w);
            int ccg = wc * 64 + j * 16 + cl, mg = wr * 32 + i * 16;
            uint4 pk;
            pk.x = h2_u32(h0); pk.y = h2_u32(h1);
            pk.z = h2_u32(h2); pk.w = h2_u32(h3);
            *(uint4*)(stage + ccg * STG_LDM + mg + boff) = pk;
            __syncwarp();
        }
    }
    __syncthreads();

    // ---- epilogue phase B: warp rr applies k2 (16x16) and stores h2r ----
    {
        const __half* k2h = (const __half*)(dsm + K2H_OFF);
        const float*  b2s = (const float*)(dsm + B2S_OFF);
        const int rr = wid, r = rh * 8 + rr;
        wmma::fragment<wmma::matrix_b, 16, 16, 16, __half, wmma::row_major> bfr;
        wmma::load_matrix_sync(bfr, k2h + rr * 256, 16);
        const int j3 = r * 4 + (j1 >> 4);
        const int k3b = (j1 & 15) * 64 + t * 16;
        float b2v[8];
        {
            int poff = (lane & 1) * 8;
#pragma unroll
            for (int q = 0; q < 8; q++) b2v[q] = b2s[rr * 16 + poff + q];
        }
#pragma unroll
        for (int mb = 0; mb < 8; mb++) {
            wmma::fragment<wmma::matrix_a, 16, 16, 16, __half, wmma::col_major> afr;
            wmma::load_matrix_sync(afr, stage + (rr * 16) * STG_LDM + mb * 16, STG_LDM);
            wmma::fragment<wmma::accumulator, 16, 16, 16, float> oc;
            wmma::fill_fragment(oc, 0.0f);
            wmma::mma_sync(oc, afr, bfr, oc);
            wmma::store_matrix_sync(wscr, oc, 16, wmma::mem_row_major);
            __syncwarp();
            int b = lane >> 1, poff = (lane & 1) * 8;
            float4 v0 = *(float4*)(wscr + b * 16 + poff);
            float4 v1 = *(float4*)(wscr + b * 16 + poff + 4);
            __half2 h0 = __floats2half2_rn(v0.x + b2v[0], v0.y + b2v[1]);
            __half2 h1 = __floats2half2_rn(v0.z + b2v[2], v0.w + b2v[3]);
            __half2 h2 = __floats2half2_rn(v1.x + b2v[4], v1.y + b2v[5]);
            __half2 h3 = __floats2half2_rn(v1.z + b2v[6], v1.w + b2v[7]);
            uint4 pk;
            pk.x = h2_u32(h0); pk.y = h2_u32(h1);
            pk.z = h2_u32(h2); pk.w = h2_u32(h3);
            *(uint4*)(g_h2r + ((size_t)j3 * 1024 + m0 + mb * 16 + b) * 1024 +
                      k3b + poff) = pk;
            __syncwarp();
        }
    }
}

// ------------------------- GEMM3 (unchanged R10) ---------------------------
template <int NC>
__device__ __forceinline__ void gemm_mainloop(
    const __half* aS, int aStride, const __half* bS, int bStride,
    char* dsm, uint32_t sbase, int tid, int wr, int wc,
    wmma::fragment<wmma::accumulator, 16, 16, 16, float> (&acc)[2][4])
{
#pragma unroll
    for (int i = 0; i < 2; i++)
#pragma unroll
        for (int j = 0; j < 4; j++) wmma::fill_fragment(acc[i][j], 0.0f);

    for (int i = tid; i < 1024; i += 256) {
        int row = i >> 3, seg = i & 7;
        cpa(sbase + A_OFF(0) + row * ROWB + seg * 16, aS + row * aStride + seg * 8);
        cpa(sbase + B_OFF(0) + row * ROWB + seg * 16, bS + row * bStride + seg * 8);
    }
    cpcommit();

    for (int c = 0; c < NC; c++) {
        const int buf = c & 1;
        if (c + 1 < NC) {
            const int nb = (c + 1) & 1, k0 = (c + 1) * 64;
            for (int i = tid; i < 1024; i += 256) {
                int row = i >> 3, seg = i & 7;
                cpa(sbase + A_OFF(nb) + row * ROWB + seg * 16,
                    aS + row * aStride + k0 + seg * 8);
                cpa(sbase + B_OFF(nb) + row * ROWB + seg * 16,
                    bS + row * bStride + k0 + seg * 8);
            }
            cpcommit();
            cpwait1();
        } else {
            cpwait0();
        }
        __syncthreads();

        const __half* As = (const __half*)(dsm + A_OFF(buf));
        const __half* Bs = (const __half*)(dsm + B_OFF(buf));
#pragma unroll
        for (int kk = 0; kk < 64; kk += 16) {
            wmma::fragment<wmma::matrix_a, 16, 16, 16, __half, wmma::row_major> af[2];
            wmma::fragment<wmma::matrix_b, 16, 16, 16, __half, wmma::col_major> bf[4];
#pragma unroll
            for (int i = 0; i < 2; i++)
                wmma::load_matrix_sync(af[i], As + (wr * 32 + i * 16) * LDM + kk, LDM);
#pragma unroll
            for (int j = 0; j < 4; j++)
                wmma::load_matrix_sync(bf[j], Bs + (wc * 64 + j * 16) * LDM + kk, LDM);
#pragma unroll
            for (int i = 0; i < 2; i++)
#pragma unroll
                for (int j = 0; j < 4; j++)
                    wmma::mma_sync(acc[i][j], af[i], bf[j], acc[i][j]);
        }
        __syncthreads();
    }
}

__global__ __launch_bounds__(256, 2) void g3(const float* __restrict__ b3,
                                             float* __restrict__ out) {
    extern __shared__ __align__(16) char dsm[];
    const int tid = threadIdx.x, wid = tid >> 5;
    const int wr = wid >> 1, wc = wid & 1;
    const int j3 = blockIdx.z, n0 = blockIdx.x * 128, m0 = blockIdx.y * 128;
    const uint32_t sbase = smem_u32(dsm);

    const __half* aS = g_h2r + ((size_t)(j3 * 1024 + m0)) * 1024;
    const __half* bS = g_k3t + ((size_t)(j3 * 256 + n0)) * 1024;

    wmma::fragment<wmma::accumulator, 16, 16, 16, float> acc[2][4];
    gemm_mainloop<16>(aS, 1024, bS, 1024, dsm, sbase, tid, wr, wc, acc);

    float* stage = (float*)dsm;
    const int b2x = j3 >> 3, b2y = j3 & 7;
#pragma unroll
    for (int h = 0; h < 2; ++h) {
        if (wc == h) {
#pragma unroll
            for (int i = 0; i < 2; i++)
#pragma unroll
                for (int j = 0; j < 4; j++)
                    wmma::store_matrix_sync(
                        stage + (wr * 32 + i * 16) * 68 + j * 16,
                        acc[i][j], 68, wmma::mem_row_major);
        }
        __syncthreads();
        for (int e = tid; e < 8192; e += 256) {
            int cc = e & 63, row = e >> 6;
            int l3 = n0 + h * 64 + cc;
            if (l3 < 200) {
                float v = stage[row * 68 + cc] + b3[j3 * 200 + l3];
                int q = l3 >> 1, c = l3 & 1;
                int w2x = q / 10, w2y = q - w2x * 10;
                out[(m0 + row) * 12800 +
                    ((b2x * 10 + w2x) * 80 + b2y * 10 + w2y) * 2 + c] = v;
            }
        }
        __syncthreads();
    }
}

extern "C" void kernel_launch(void* const* d_in, const int* in_sizes, int n_in,
                              void* d_out, int out_size) {
    const float* x   = (const float*)d_in[0];
    const float* k1  = (const float*)d_in[1];
    const float* b1  = (const float*)d_in[2];
    const float* k2  = (const float*)d_in[3];
    const float* b2  = (const float*)d_in[4];
    const float* k3w = (const float*)d_in[5];
    const float* b3  = (const float*)d_in[6];
    float* out = (float*)d_out;

    cudaFuncSetAttribute(g1f, cudaFuncAttributeMaxDynamicSharedMemorySize, G1F_SMEM);
    cudaFuncSetAttribute(g3,  cudaFuncAttributeMaxDynamicSharedMemorySize, SMEM_BYTES);

    gather_x    <<<dim3(1024, 8), 256>>>(x);
    transpose_k1<<<dim3(32, 8, 64), dim3(32, 8)>>>(k1);
    transpose_k3<<<dim3(32, 8, 64), dim3(32, 8)>>>(k3w);
    biasprep    <<<4096, 32>>>(b1, k2, b2);
    g1f<<<dim3(8, 8, 64), 256, G1F_SMEM>>>(k2);
    g3 <<<dim3(2, 8, 64), 256, SMEM_BYTES>>>(b3, out);
}